// round 16
// baseline (speedup 1.0000x reference)
#include <cuda_runtime.h>
#include <cuda_bf16.h>

// LearnablePeakExtractor: smooth = x * sig(10*(x-thresh)) * sig(10*(x-pooled5))
//                         mask   = smooth >= thresh
// Fused: sig(a)*sig(b) = 1/((1+e^-a)(1+e^-b)) -> 2 EX2 + 1 RCP per element.
// R16: R5 body (best, 63.55/63.81us) with grid axes swapped — consecutive
//      CTAs process the SAME chunk position in DIFFERENT rows (512 KiB
//      stride), spreading each resident wave across all HBM channels and
//      both L2 dies instead of one contiguous ~19 MB span.

#define ROWS 256
#define LEN  131072
#define CH   (LEN / 8)   // 8-elem chunks per row = 16384

__device__ __forceinline__ float fused2(float x, float thresh, float pooled) {
    float e1 = __expf(10.0f * (thresh - x));
    float e2 = __expf(10.0f * (pooled - x));
    return __fdividef(x, (1.0f + e1) * (1.0f + e2));
}

__device__ __forceinline__ void ldg256(const float* p, float* r) {
    asm volatile("ld.global.v8.f32 {%0,%1,%2,%3,%4,%5,%6,%7}, [%8];"
                 : "=f"(r[0]), "=f"(r[1]), "=f"(r[2]), "=f"(r[3]),
                   "=f"(r[4]), "=f"(r[5]), "=f"(r[6]), "=f"(r[7])
                 : "l"(p));
}

__device__ __forceinline__ void stg256(float* p, const float* r) {
    asm volatile("st.global.v8.f32 [%0], {%1,%2,%3,%4,%5,%6,%7,%8};"
                 :: "l"(p),
                    "f"(r[0]), "f"(r[1]), "f"(r[2]), "f"(r[3]),
                    "f"(r[4]), "f"(r[5]), "f"(r[6]), "f"(r[7])
                 : "memory");
}

__global__ __launch_bounds__(256)
void peak_kernel(const float* __restrict__ in,
                 const float* __restrict__ logit_thresh,
                 float* __restrict__ out_smooth,
                 float* __restrict__ out_mask,
                 int write_mask)
{
    // Swapped mapping: x = row (fast-iterating), y = chunk-group.
    const int row = blockIdx.x;
    const int t   = blockIdx.y * blockDim.x + threadIdx.x;   // chunk index in row
    const unsigned lane = threadIdx.x & 31;

    const float* rowp = in + (size_t)row * LEN;
    const float* base = rowp + 8 * (size_t)t;

    float e[8];
    ldg256(base, e);

    // halo via warp shuffle; only warp-edge lanes touch memory
    float lx = __shfl_up_sync(0xFFFFFFFFu,   e[6], 1);
    float ly = __shfl_up_sync(0xFFFFFFFFu,   e[7], 1);
    float rx = __shfl_down_sync(0xFFFFFFFFu, e[0], 1);
    float ry = __shfl_down_sync(0xFFFFFFFFu, e[1], 1);

    if (lane == 0) {
        if (t > 0) {
            float2 p = *reinterpret_cast<const float2*>(base - 2);
            lx = p.x; ly = p.y;
        } else {
            lx = e[0]; ly = e[0];    // edge replicate
        }
    }
    if (lane == 31) {
        if (t < CH - 1) {
            float2 n = *reinterpret_cast<const float2*>(base + 8);
            rx = n.x; ry = n.y;
        } else {
            rx = e[7]; ry = e[7];    // edge replicate
        }
    }

    // 5-wide sliding max over e[0..7] with halo (lx,ly | rx,ry)
    float M01 = fmaxf(e[0], e[1]);
    float M23 = fmaxf(e[2], e[3]);
    float M45 = fmaxf(e[4], e[5]);
    float M67 = fmaxf(e[6], e[7]);
    float Mll = fmaxf(lx, ly);
    float Mrr = fmaxf(rx, ry);

    float p[8];
    p[0] = fmaxf(Mll,  fmaxf(M01, e[2]));
    p[1] = fmaxf(ly,   fmaxf(M01, M23));
    p[2] = fmaxf(M01,  fmaxf(M23, e[4]));
    p[3] = fmaxf(e[1], fmaxf(M23, M45));
    p[4] = fmaxf(e[2], fmaxf(M23, fmaxf(M45, e[6])));
    p[5] = fmaxf(e[3], fmaxf(M45, M67));
    p[6] = fmaxf(M45,  fmaxf(M67, rx));
    p[7] = fmaxf(e[5], fmaxf(M67, Mrr));

    float tl = logit_thresh[0];
    float thresh = __fdividef(1.0f, 1.0f + __expf(-tl));

    float s[8];
#pragma unroll
    for (int i = 0; i < 8; i++)
        s[i] = fused2(e[i], thresh, p[i]);

    const size_t off = (size_t)row * LEN + 8 * (size_t)t;
    stg256(out_smooth + off, s);

    if (write_mask) {
        float m[8];
#pragma unroll
        for (int i = 0; i < 8; i++)
            m[i] = (s[i] >= thresh) ? 1.0f : 0.0f;
        stg256(out_mask + off, m);
    }
}

extern "C" void kernel_launch(void* const* d_in, const int* in_sizes, int n_in,
                              void* d_out, int out_size)
{
    const float* peak_map     = (const float*)d_in[0];
    const float* logit_thresh = (const float*)d_in[1];
    float* out = (float*)d_out;

    const long long N = (long long)ROWS * LEN;   // 33,554,432
    int write_mask = (out_size >= 2 * N) ? 1 : 0;

    dim3 grid(ROWS, CH / 256);   // (256, 64) — x=row, y=chunk-group
    peak_kernel<<<grid, 256>>>(peak_map, logit_thresh,
                               out, out + N, write_mask);
}

// round 17
// speedup vs baseline: 1.0317x; 1.0317x over previous
#include <cuda_runtime.h>
#include <cuda_bf16.h>

// LearnablePeakExtractor: smooth = x * sig(10*(x-thresh)) * sig(10*(x-pooled5))
//                         mask   = smooth >= thresh
// Fused: sig(a)*sig(b) = 1/((1+e^-a)(1+e^-b)) -> 2 EX2 + 1 RCP per element.
// FINAL (= R5/R15, best measured 63.55/63.81us @ ~73% HBM):
//   - 256-bit ld/st (LDG.E.256 / STG.E.256), 8 floats/thread
//   - warp-shuffle halo (only warp-edge lanes do 8B halo loads)
//   - 256-thread blocks, contiguous grid order (x=chunk-group, y=row)
// Swept and rejected: vec4 (64.0), tile 2x (67.6), .cs stores (66.3),
// MLP=2 dual-row (64.1), persistent grid (74.5), evict_last loads (64.3),
// 128/512 TPB (69.7/64.3), grid-axis swap (65.6). Kernel is pinned at the
// chip's mixed 1:2 R:W HBM streaming ceiling with minimal traffic
// (128 MiB read + 256 MiB write); compute fully hidden.

#define ROWS 256
#define LEN  131072
#define CH   (LEN / 8)   // 8-elem chunks per row = 16384

__device__ __forceinline__ float fused2(float x, float thresh, float pooled) {
    float e1 = __expf(10.0f * (thresh - x));
    float e2 = __expf(10.0f * (pooled - x));
    return __fdividef(x, (1.0f + e1) * (1.0f + e2));
}

__device__ __forceinline__ void ldg256(const float* p, float* r) {
    asm volatile("ld.global.v8.f32 {%0,%1,%2,%3,%4,%5,%6,%7}, [%8];"
                 : "=f"(r[0]), "=f"(r[1]), "=f"(r[2]), "=f"(r[3]),
                   "=f"(r[4]), "=f"(r[5]), "=f"(r[6]), "=f"(r[7])
                 : "l"(p));
}

__device__ __forceinline__ void stg256(float* p, const float* r) {
    asm volatile("st.global.v8.f32 [%0], {%1,%2,%3,%4,%5,%6,%7,%8};"
                 :: "l"(p),
                    "f"(r[0]), "f"(r[1]), "f"(r[2]), "f"(r[3]),
                    "f"(r[4]), "f"(r[5]), "f"(r[6]), "f"(r[7])
                 : "memory");
}

__global__ __launch_bounds__(256)
void peak_kernel(const float* __restrict__ in,
                 const float* __restrict__ logit_thresh,
                 float* __restrict__ out_smooth,
                 float* __restrict__ out_mask,
                 int write_mask)
{
    const int row = blockIdx.y;
    const int t   = blockIdx.x * blockDim.x + threadIdx.x;   // chunk index in row
    const unsigned lane = threadIdx.x & 31;

    const float* rowp = in + (size_t)row * LEN;
    const float* base = rowp + 8 * (size_t)t;

    float e[8];
    ldg256(base, e);

    // halo via warp shuffle; only warp-edge lanes touch memory
    float lx = __shfl_up_sync(0xFFFFFFFFu,   e[6], 1);
    float ly = __shfl_up_sync(0xFFFFFFFFu,   e[7], 1);
    float rx = __shfl_down_sync(0xFFFFFFFFu, e[0], 1);
    float ry = __shfl_down_sync(0xFFFFFFFFu, e[1], 1);

    if (lane == 0) {
        if (t > 0) {
            float2 p = *reinterpret_cast<const float2*>(base - 2);
            lx = p.x; ly = p.y;
        } else {
            lx = e[0]; ly = e[0];    // edge replicate
        }
    }
    if (lane == 31) {
        if (t < CH - 1) {
            float2 n = *reinterpret_cast<const float2*>(base + 8);
            rx = n.x; ry = n.y;
        } else {
            rx = e[7]; ry = e[7];    // edge replicate
        }
    }

    // 5-wide sliding max over e[0..7] with halo (lx,ly | rx,ry)
    float M01 = fmaxf(e[0], e[1]);
    float M23 = fmaxf(e[2], e[3]);
    float M45 = fmaxf(e[4], e[5]);
    float M67 = fmaxf(e[6], e[7]);
    float Mll = fmaxf(lx, ly);
    float Mrr = fmaxf(rx, ry);

    float p[8];
    p[0] = fmaxf(Mll,  fmaxf(M01, e[2]));
    p[1] = fmaxf(ly,   fmaxf(M01, M23));
    p[2] = fmaxf(M01,  fmaxf(M23, e[4]));
    p[3] = fmaxf(e[1], fmaxf(M23, M45));
    p[4] = fmaxf(e[2], fmaxf(M23, fmaxf(M45, e[6])));
    p[5] = fmaxf(e[3], fmaxf(M45, M67));
    p[6] = fmaxf(M45,  fmaxf(M67, rx));
    p[7] = fmaxf(e[5], fmaxf(M67, Mrr));

    float tl = logit_thresh[0];
    float thresh = __fdividef(1.0f, 1.0f + __expf(-tl));

    float s[8];
#pragma unroll
    for (int i = 0; i < 8; i++)
        s[i] = fused2(e[i], thresh, p[i]);

    const size_t off = (size_t)row * LEN + 8 * (size_t)t;
    stg256(out_smooth + off, s);

    if (write_mask) {
        float m[8];
#pragma unroll
        for (int i = 0; i < 8; i++)
            m[i] = (s[i] >= thresh) ? 1.0f : 0.0f;
        stg256(out_mask + off, m);
    }
}

extern "C" void kernel_launch(void* const* d_in, const int* in_sizes, int n_in,
                              void* d_out, int out_size)
{
    const float* peak_map     = (const float*)d_in[0];
    const float* logit_thresh = (const float*)d_in[1];
    float* out = (float*)d_out;

    const long long N = (long long)ROWS * LEN;   // 33,554,432
    int write_mask = (out_size >= 2 * N) ? 1 : 0;

    dim3 grid(CH / 256, ROWS);   // (64, 256)
    peak_kernel<<<grid, 256>>>(peak_map, logit_thresh,
                               out, out + N, write_mask);
}